// round 1
// baseline (speedup 1.0000x reference)
#include <cuda_runtime.h>

// ---------------------------------------------------------------------------
// PCritical step, B=32, N=4096.
// Outputs concatenated float32 in reference return order:
//   S (B,N) | mem_pot_n (B,N) | W_new (N,N) | mem_cur_n (B,N) |
//   mem_pot_p_n (B,N) | mem_cur_p_n (B,N) | refrac_new (B,N)
// ---------------------------------------------------------------------------

#define Bsz 32
#define Nsz 4096
#define BN  (Bsz * Nsz)        // 131072
#define NN  (Nsz * Nsz)        // 16777216

#define C_ALPHA 0.025f
#define C_BETA  0.00025f
#define C_TNOW  10.0f
#define C_INV_TAU_V 0.9801986733067553f
#define C_INV_TAU_I 0.36787944117144233f

#define OUT_S    ((long long)0)
#define OUT_POT  ((long long)BN)
#define OUT_W    ((long long)(2LL * BN))
#define OUT_CUR  ((long long)(2LL * BN + NN))
#define OUT_POTP ((long long)(3LL * BN + NN))
#define OUT_CURP ((long long)(4LL * BN + NN))
#define OUT_REFR ((long long)(5LL * BN + NN))

// scratch (no dynamic allocation allowed)
__device__ __align__(16) unsigned g_masks[Nsz];     // bit b set <=> S[b,n] == 1
__device__ __align__(16) float    g_e[Nsz];          // exp(max_st/50)
__device__ __align__(16) float    g_ie[Nsz];         // exp(-max_st/50)
__device__ __align__(16) float    g_A[Nsz];          // sp_flag ? ALPHA*e  : 0
__device__ __align__(16) float    g_Ai[Nsz];         // sp_flag ? ALPHA*ie : 0
__device__ __align__(16) float    g_accP[4 * BN];    // partials of S@W_new
__device__ __align__(16) float    g_accTP[4 * BN];   // partials of S@W_new^T

// ---------------------------------------------------------------------------
// K1: per-neuron reductions over the batch + exp precompute
// ---------------------------------------------------------------------------
__global__ void __launch_bounds__(256) k_prologue(
    const float* __restrict__ mem_pot,
    const float* __restrict__ mem_pot_paired,
    const float* __restrict__ st)
{
    int n = blockIdx.x * 256 + threadIdx.x;   // grid covers exactly Nsz
    unsigned m = 0u;
    bool anyp = false;
#pragma unroll
    for (int b = 0; b < Bsz; ++b) {
        float mp = mem_pot[b * Nsz + n];
        if (mp > 1.0f) m |= (1u << b);                      // S = clip(ceil(mp-1),0,1)
        float mpp = mem_pot_paired[b * Nsz + n];
        if (((mpp - 1.0f) - C_ALPHA) > 0.0f) anyp = true;   // S_paired
    }
    float stn = st[n];
    // st_new = where(S>0, T_NOW, st); max over batch:
    float maxst = (m == 0xffffffffu) ? C_TNOW
                : (m ? fmaxf(C_TNOW, stn) : stn);
    float e  = expf(maxst * (1.0f / 50.0f));
    float ie = expf(-maxst * (1.0f / 50.0f));
    g_masks[n] = m;
    g_e[n]  = e;
    g_ie[n] = ie;
    g_A[n]  = anyp ? C_ALPHA * e  : 0.0f;
    g_Ai[n] = anyp ? C_ALPHA * ie : 0.0f;
}

// ---------------------------------------------------------------------------
// K2: W_new elementwise (float4 vectorized), 128 MB traffic, DRAM-bound
//   exp(|a-b|/50) = max(e_i*ie_j, ie_i*e_j)
// ---------------------------------------------------------------------------
__device__ __forceinline__ float upd1(float w, float A, float Ai, float e, float ie)
{
    float sub = fmaxf(A * ie, Ai * e);        // 0 when row not spiking-paired
    float u = (w + C_BETA) - sub;
    u = fminf(fmaxf(u, 0.0f), 1.0f);
    return (w > 0.0f) ? u : w;                // sign_mask = W_rec > 0
}

__global__ void __launch_bounds__(256) k_wpass(
    const float* __restrict__ W, float* __restrict__ Wout)
{
    int t = blockIdx.x * 256 + threadIdx.x;   // NN/4 threads
    int v = t * 4;
    int i = v >> 12;
    int j = v & (Nsz - 1);
    float4 w = __ldg((const float4*)(W + v));
    float A  = g_A[i];
    float Ai = g_Ai[i];
    float4 e  = *(const float4*)(g_e + j);
    float4 ie = *(const float4*)(g_ie + j);
    float4 o;
    o.x = upd1(w.x, A, Ai, e.x, ie.x);
    o.y = upd1(w.y, A, Ai, e.y, ie.y);
    o.z = upd1(w.z, A, Ai, e.z, ie.z);
    o.w = upd1(w.w, A, Ai, e.w, ie.w);
    *(float4*)(Wout + v) = o;
}

// ---------------------------------------------------------------------------
// K3: acc[b][j] = sum_i S[b,i] * W_new[i,j]  (binary S -> predicated f32x2 adds)
// grid: 256 blocks = 4 i-chunks x 64 j-blocks(64 cols). warp lane = b,
// each thread owns 8 consecutive j (4 packed f32x2 accumulators).
// ---------------------------------------------------------------------------
__global__ void __launch_bounds__(256) k_acc(const float* __restrict__ Wn)
{
    __shared__ __align__(16) unsigned sm[1024];
    int ic = blockIdx.x >> 6;     // i chunk 0..3 (1024 rows each)
    int jb = blockIdx.x & 63;     // 64-column block
    for (int k = threadIdx.x; k < 1024; k += 256)
        sm[k] = g_masks[ic * 1024 + k];
    __syncthreads();

    int b  = threadIdx.x & 31;
    int w  = threadIdx.x >> 5;    // 0..7
    int j0 = jb * 64 + w * 8;

    unsigned long long a0 = 0, a1 = 0, a2 = 0, a3 = 0;
    const ulonglong2* base =
        (const ulonglong2*)(Wn + (size_t)ic * 1024 * Nsz + j0);
    // row stride = 4096 floats = 1024 ulonglong2

#pragma unroll 4
    for (int ii = 0; ii < 1024; ++ii) {
        unsigned m  = sm[ii];
        unsigned pb = (m >> b) & 1u;
        ulonglong2 d0 = __ldg(base + (size_t)ii * 1024);
        ulonglong2 d1 = __ldg(base + (size_t)ii * 1024 + 1);
        asm("{\n\t"
            ".reg .pred p;\n\t"
            "setp.ne.u32 p, %4, 0;\n\t"
            "@p add.rn.f32x2 %0, %0, %5;\n\t"
            "@p add.rn.f32x2 %1, %1, %6;\n\t"
            "@p add.rn.f32x2 %2, %2, %7;\n\t"
            "@p add.rn.f32x2 %3, %3, %8;\n\t"
            "}"
            : "+l"(a0), "+l"(a1), "+l"(a2), "+l"(a3)
            : "r"(pb), "l"(d0.x), "l"(d0.y), "l"(d1.x), "l"(d1.y));
    }

    size_t o = (size_t)(ic * Bsz + b) * Nsz + j0;   // partials [ic][b][j]
    ulonglong2* outp = (ulonglong2*)(g_accP + o);
    outp[0] = make_ulonglong2(a0, a1);
    outp[1] = make_ulonglong2(a2, a3);
}

// ---------------------------------------------------------------------------
// K4: accT[b][i] = sum_j S[b,j] * W_new[i,j]
// grid: 256 blocks = 4 j-chunks x 64 i-blocks(64 rows). warp lane = b,
// thread owns 8 rows (scalar accumulators), loops j in quads with LDG.128.
// Strided row loads get sector reuse across the 4-j quad via L1.
// ---------------------------------------------------------------------------
__global__ void __launch_bounds__(256) k_accT(const float* __restrict__ Wn)
{
    __shared__ __align__(16) unsigned sm[1024];
    int jc = blockIdx.x >> 6;     // j chunk 0..3 (1024 cols each)
    int ib = blockIdx.x & 63;     // 64-row block
    for (int k = threadIdx.x; k < 1024; k += 256)
        sm[k] = g_masks[jc * 1024 + k];
    __syncthreads();

    int b  = threadIdx.x & 31;
    int w  = threadIdx.x >> 5;
    int i0 = ib * 64 + w * 8;
    unsigned bit = 1u << b;

    float acc0 = 0, acc1 = 0, acc2 = 0, acc3 = 0;
    float acc4 = 0, acc5 = 0, acc6 = 0, acc7 = 0;

    const float4* r0 = (const float4*)(Wn + (size_t)i0 * Nsz) + jc * 256;
    // row stride = 1024 float4

#pragma unroll 2
    for (int q = 0; q < 256; ++q) {
        uint4 m4 = *((const uint4*)sm + q);
        float4 v0 = __ldg(r0 + q);
        float4 v1 = __ldg(r0 + 1 * 1024 + q);
        float4 v2 = __ldg(r0 + 2 * 1024 + q);
        float4 v3 = __ldg(r0 + 3 * 1024 + q);
        float4 v4 = __ldg(r0 + 4 * 1024 + q);
        float4 v5 = __ldg(r0 + 5 * 1024 + q);
        float4 v6 = __ldg(r0 + 6 * 1024 + q);
        float4 v7 = __ldg(r0 + 7 * 1024 + q);
        unsigned mm[4] = {m4.x, m4.y, m4.z, m4.w};
        const float* p0 = &v0.x; const float* p1 = &v1.x;
        const float* p2 = &v2.x; const float* p3 = &v3.x;
        const float* p4 = &v4.x; const float* p5 = &v5.x;
        const float* p6 = &v6.x; const float* p7 = &v7.x;
#pragma unroll
        for (int k = 0; k < 4; ++k) {
            if (mm[k] & bit) {
                acc0 += p0[k]; acc1 += p1[k]; acc2 += p2[k]; acc3 += p3[k];
                acc4 += p4[k]; acc5 += p5[k]; acc6 += p6[k]; acc7 += p7[k];
            }
        }
    }

    size_t o = (size_t)(jc * Bsz + b) * Nsz + i0;   // partials [jc][b][i]
    float4 s0 = make_float4(acc0, acc1, acc2, acc3);
    float4 s1 = make_float4(acc4, acc5, acc6, acc7);
    *((float4*)(g_accTP + o))     = s0;
    *((float4*)(g_accTP + o + 4)) = s1;
}

// ---------------------------------------------------------------------------
// K5: epilogue — integrate, leak, reset, refractory; write all (B,N) outputs
// ---------------------------------------------------------------------------
__global__ void __launch_bounds__(256) k_epilogue(
    const float* __restrict__ inp,
    const float* __restrict__ mem_pot,
    const float* __restrict__ mem_cur,
    const float* __restrict__ mem_pot_paired,
    const float* __restrict__ mem_cur_paired,
    const int*   __restrict__ refrac,
    float* __restrict__ out)
{
    int t = blockIdx.x * 256 + threadIdx.x;   // BN threads
    int b = t >> 12;
    int n = t & (Nsz - 1);

    int r  = refrac[t];
    int rd = (r > 0) ? (r - 1) : r;
    bool active = (rd == 0);

    unsigned m = g_masks[n];
    bool s  = ((m >> b) & 1u) != 0u;
    float mppv = mem_pot_paired[t];
    bool sp = ((mppv - 1.0f) - C_ALPHA) > 0.0f;

    float acc  = g_accP[t]  + g_accP[BN + t]  + g_accP[2 * BN + t]  + g_accP[3 * BN + t];
    float accT = g_accTP[t] + g_accTP[BN + t] + g_accTP[2 * BN + t] + g_accTP[3 * BN + t];

    float mp   = mem_pot[t];
    float mc   = mem_cur[t];
    float mcpv = mem_cur_paired[t];

    float mcn  = active ? (inp[t] + acc) + mc : mc;
    float mcpn = active ? accT + mcpv : mcpv;
    float mpn  = active ? mcn + mp : mp;
    float mppn = active ? mcpn + mppv : mppv;

    mpn  *= C_INV_TAU_V;
    mcn  *= C_INV_TAU_I;
    mppn *= C_INV_TAU_V;
    mcpn *= C_INV_TAU_I;

    if (s)  mpn  = 0.0f;
    if (sp) mppn = 0.0f;
    float rn = s ? 2.0f : (float)rd;

    out[OUT_S    + t] = s ? 1.0f : 0.0f;
    out[OUT_POT  + t] = mpn;
    out[OUT_CUR  + t] = mcn;
    out[OUT_POTP + t] = mppn;
    out[OUT_CURP + t] = mcpn;
    out[OUT_REFR + t] = rn;
}

// ---------------------------------------------------------------------------
extern "C" void kernel_launch(void* const* d_in, const int* in_sizes, int n_in,
                              void* d_out, int out_size)
{
    const float* inp      = (const float*)d_in[0];
    const float* W_rec    = (const float*)d_in[1];
    const float* mem_pot  = (const float*)d_in[2];
    const float* mem_cur  = (const float*)d_in[3];
    const float* mpp      = (const float*)d_in[4];
    const float* mcp      = (const float*)d_in[5];
    const float* st       = (const float*)d_in[6];
    const int*   refrac   = (const int*)d_in[7];
    float* out = (float*)d_out;
    float* Wout = out + OUT_W;

    k_prologue<<<Nsz / 256, 256>>>(mem_pot, mpp, st);
    k_wpass<<<NN / 4 / 256, 256>>>(W_rec, Wout);
    k_acc<<<256, 256>>>(Wout);
    k_accT<<<256, 256>>>(Wout);
    k_epilogue<<<BN / 256, 256>>>(inp, mem_pot, mem_cur, mpp, mcp, refrac, out);
}

// round 2
// speedup vs baseline: 2.1711x; 2.1711x over previous
#include <cuda_runtime.h>

// ---------------------------------------------------------------------------
// PCritical step, B=32, N=4096 — fused single pass over W.
// Outputs concatenated float32 in reference return order:
//   S (B,N) | mem_pot_n (B,N) | W_new (N,N) | mem_cur_n (B,N) |
//   mem_pot_p_n (B,N) | mem_cur_p_n (B,N) | refrac_new (B,N)
// ---------------------------------------------------------------------------

#define Bsz 32
#define Nsz 4096
#define BN  (Bsz * Nsz)        // 131072
#define NN  (Nsz * Nsz)        // 16777216

#define C_ALPHA 0.025f
#define C_BETA  0.00025f
#define C_TNOW  10.0f
#define C_INV_TAU_V 0.9801986733067553f
#define C_INV_TAU_I 0.36787944117144233f

#define OUT_S    ((long long)0)
#define OUT_POT  ((long long)BN)
#define OUT_W    ((long long)(2LL * BN))
#define OUT_CUR  ((long long)(2LL * BN + NN))
#define OUT_POTP ((long long)(3LL * BN + NN))
#define OUT_CURP ((long long)(4LL * BN + NN))
#define OUT_REFR ((long long)(5LL * BN + NN))

// fused-kernel tiling: block covers 256 i x 128 j (2 subtiles of 128x128)
#define ICHUNKS 16             // 4096 / 256
#define JCHUNKS 32             // 4096 / 128
#define PAD2    130            // transposed smem pitch (2-way conflict, 8B align)

// scratch (no dynamic allocation allowed)
__device__ __align__(16) unsigned g_masks[Nsz];          // bit b <=> S[b,n]==1
__device__ __align__(16) float    g_e[Nsz];              // exp(max_st/50)
__device__ __align__(16) float    g_ie[Nsz];             // exp(-max_st/50)
__device__ __align__(16) float    g_A[Nsz];              // sp ? ALPHA*e  : 0
__device__ __align__(16) float    g_Ai[Nsz];             // sp ? ALPHA*ie : 0
__device__ __align__(16) float    g_accP[ICHUNKS * BN];  // partials S@W_new
__device__ __align__(16) float    g_accTP[JCHUNKS * BN]; // partials S@W_new^T

// ---------------------------------------------------------------------------
// K1: per-neuron reductions over the batch + exp precompute
// ---------------------------------------------------------------------------
__global__ void __launch_bounds__(256) k_prologue(
    const float* __restrict__ mem_pot,
    const float* __restrict__ mem_pot_paired,
    const float* __restrict__ st)
{
    int n = blockIdx.x * 256 + threadIdx.x;
    unsigned m = 0u;
    bool anyp = false;
#pragma unroll
    for (int b = 0; b < Bsz; ++b) {
        float mp = mem_pot[b * Nsz + n];
        if (mp > 1.0f) m |= (1u << b);
        float mpp = mem_pot_paired[b * Nsz + n];
        if (((mpp - 1.0f) - C_ALPHA) > 0.0f) anyp = true;
    }
    float stn = st[n];
    float maxst = (m == 0xffffffffu) ? C_TNOW
                : (m ? fmaxf(C_TNOW, stn) : stn);
    float e  = expf(maxst * (1.0f / 50.0f));
    float ie = expf(-maxst * (1.0f / 50.0f));
    g_masks[n] = m;
    g_e[n]  = e;
    g_ie[n] = ie;
    g_A[n]  = anyp ? C_ALPHA * e  : 0.0f;
    g_Ai[n] = anyp ? C_ALPHA * ie : 0.0f;
}

__device__ __forceinline__ float upd1(float w, float A, float Ai, float e, float ie)
{
    float sub = fmaxf(A * ie, Ai * e);        // 0 when row not paired-spiking
    float u = (w + C_BETA) - sub;
    u = fminf(fmaxf(u, 0.0f), 1.0f);
    return (w > 0.0f) ? u : w;                // sign_mask = W_rec > 0
}

// ---------------------------------------------------------------------------
// K2 (fused): W update + both binary-S GEMMs, single pass over W.
// 512 threads. Block tile: 256 i x 128 j, processed as 2 subtiles 128x128.
//   Phase A: coalesced read W_rec, update, write W_new + smem c1 (row-major)
//            + smem c2 (transposed, pitch 130).
//   Phase B: acc[b][j]  += W_new[i][j] where S[b,i]  (broadcast LDS.128 + padd)
//   Phase C: accT[b][i] += W_new[i][j] where S[b,j]  (broadcast LDS.64  + padd)
// Deterministic chunked partials to g_accP / g_accTP.
// ---------------------------------------------------------------------------
__global__ void __launch_bounds__(512) k_fused(
    const float* __restrict__ W, float* __restrict__ Wout)
{
    extern __shared__ float sm[];
    float*    c1 = sm;                 // [128][128]
    float*    c2 = sm + 16384;         // [128][PAD2] transposed: c2[j*130+i]
    unsigned* mi = (unsigned*)(sm + 16384 + 128 * PAD2);   // 128 row masks
    unsigned* mj = mi + 128;                               // 128 col masks

    const int jc   = blockIdx.x;       // 0..31
    const int ic   = blockIdx.y;       // 0..15
    const int tid  = threadIdx.x;
    const int warp = tid >> 5;         // 0..15
    const int lane = tid & 31;

    const int jg0 = jc * 128;

    // column masks + per-column exp factors (hoisted; j fixed for the block)
    if (tid < 128) mj[tid] = g_masks[jg0 + tid];

    float e0  = g_e[jg0 + lane];       float ie0 = g_ie[jg0 + lane];
    float e1  = g_e[jg0 + lane + 32];  float ie1 = g_ie[jg0 + lane + 32];
    float e2  = g_e[jg0 + lane + 64];  float ie2 = g_ie[jg0 + lane + 64];
    float e3  = g_e[jg0 + lane + 96];  float ie3 = g_ie[jg0 + lane + 96];

    // accumulators: phase B (8 j per warp, persists over both subtiles)
    unsigned long long aJ0 = 0, aJ1 = 0, aJ2 = 0, aJ3 = 0;

#pragma unroll
    for (int s = 0; s < 2; ++s) {
        if (s) __syncthreads();        // protect smem from previous readers

        const int ig0 = ic * 256 + s * 128;    // global row base of subtile

        if (tid < 128) mi[tid] = g_masks[ig0 + tid];

        // ---- Phase A: update 128 rows; warp w owns rows {w, w+16, ...} ----
#pragma unroll
        for (int r = 0; r < 8; ++r) {
            int il = warp + 16 * r;
            int ig = ig0 + il;
            float A  = g_A[ig];
            float Ai = g_Ai[ig];
            const float* wr = W    + (size_t)ig * Nsz + jg0;
            float*       wo = Wout + (size_t)ig * Nsz + jg0;
            float w0 = wr[lane];
            float w1 = wr[lane + 32];
            float w2 = wr[lane + 64];
            float w3 = wr[lane + 96];
            float u0 = upd1(w0, A, Ai, e0, ie0);
            float u1 = upd1(w1, A, Ai, e1, ie1);
            float u2 = upd1(w2, A, Ai, e2, ie2);
            float u3 = upd1(w3, A, Ai, e3, ie3);
            wo[lane]      = u0;
            wo[lane + 32] = u1;
            wo[lane + 64] = u2;
            wo[lane + 96] = u3;
            float* c1r = c1 + il * 128;
            c1r[lane]      = u0;
            c1r[lane + 32] = u1;
            c1r[lane + 64] = u2;
            c1r[lane + 96] = u3;
            c2[(lane)      * PAD2 + il] = u0;
            c2[(lane + 32) * PAD2 + il] = u1;
            c2[(lane + 64) * PAD2 + il] = u2;
            c2[(lane + 96) * PAD2 + il] = u3;
        }
        __syncthreads();

        // ---- Phase B: acc over rows (pred on row mask, lane = batch b) ----
        {
            const ulonglong2* cp = (const ulonglong2*)c1;  // 32 ull2 per row
            const uint4* mp4 = (const uint4*)mi;
            int base = warp * 2;                           // j-slice offset
#pragma unroll 4
            for (int q = 0; q < 32; ++q) {
                uint4 mm = mp4[q];
                unsigned msk[4] = { mm.x, mm.y, mm.z, mm.w };
#pragma unroll
                for (int k = 0; k < 4; ++k) {
                    int il = q * 4 + k;
                    unsigned pb = (msk[k] >> lane) & 1u;
                    ulonglong2 d0 = cp[il * 32 + base];
                    ulonglong2 d1 = cp[il * 32 + base + 1];
                    asm("{\n\t"
                        ".reg .pred p;\n\t"
                        "setp.ne.u32 p, %4, 0;\n\t"
                        "@p add.rn.f32x2 %0, %0, %5;\n\t"
                        "@p add.rn.f32x2 %1, %1, %6;\n\t"
                        "@p add.rn.f32x2 %2, %2, %7;\n\t"
                        "@p add.rn.f32x2 %3, %3, %8;\n\t"
                        "}"
                        : "+l"(aJ0), "+l"(aJ1), "+l"(aJ2), "+l"(aJ3)
                        : "r"(pb), "l"(d0.x), "l"(d0.y), "l"(d1.x), "l"(d1.y));
                }
            }
        }

        // ---- Phase C: accT over cols (pred on col mask, lane = batch b) ----
        {
            unsigned long long aI0 = 0, aI1 = 0, aI2 = 0, aI3 = 0;
            const uint4* mp4 = (const uint4*)mj;
            int ib = warp * 8;                             // i-slice
#pragma unroll 4
            for (int q = 0; q < 32; ++q) {
                uint4 mm = mp4[q];
                unsigned msk[4] = { mm.x, mm.y, mm.z, mm.w };
#pragma unroll
                for (int k = 0; k < 4; ++k) {
                    int jl = q * 4 + k;
                    unsigned pb = (msk[k] >> lane) & 1u;
                    const unsigned long long* qp =
                        (const unsigned long long*)(c2 + jl * PAD2 + ib);
                    unsigned long long d0 = qp[0];
                    unsigned long long d1 = qp[1];
                    unsigned long long d2 = qp[2];
                    unsigned long long d3 = qp[3];
                    asm("{\n\t"
                        ".reg .pred p;\n\t"
                        "setp.ne.u32 p, %4, 0;\n\t"
                        "@p add.rn.f32x2 %0, %0, %5;\n\t"
                        "@p add.rn.f32x2 %1, %1, %6;\n\t"
                        "@p add.rn.f32x2 %2, %2, %7;\n\t"
                        "@p add.rn.f32x2 %3, %3, %8;\n\t"
                        "}"
                        : "+l"(aI0), "+l"(aI1), "+l"(aI2), "+l"(aI3)
                        : "r"(pb), "l"(d0), "l"(d1), "l"(d2), "l"(d3));
                }
            }
            // write accT partial slice: [jc][b=lane][i = ig0 + ib .. +8)
            size_t o = ((size_t)jc * Bsz + lane) * Nsz + ig0 + ib;
            ulonglong2* outp = (ulonglong2*)(g_accTP + o);
            outp[0] = make_ulonglong2(aI0, aI1);
            outp[1] = make_ulonglong2(aI2, aI3);
        }
    }

    // write acc partial slice: [ic][b=lane][j = jg0 + warp*8 .. +8)
    {
        size_t o = ((size_t)ic * Bsz + lane) * Nsz + jg0 + warp * 8;
        ulonglong2* outp = (ulonglong2*)(g_accP + o);
        outp[0] = make_ulonglong2(aJ0, aJ1);
        outp[1] = make_ulonglong2(aJ2, aJ3);
    }
}

// ---------------------------------------------------------------------------
// K3: epilogue — reduce partials, integrate, leak, reset, refractory
// ---------------------------------------------------------------------------
__global__ void __launch_bounds__(256) k_epilogue(
    const float* __restrict__ inp,
    const float* __restrict__ mem_pot,
    const float* __restrict__ mem_cur,
    const float* __restrict__ mem_pot_paired,
    const float* __restrict__ mem_cur_paired,
    const int*   __restrict__ refrac,
    float* __restrict__ out)
{
    int t = blockIdx.x * 256 + threadIdx.x;   // BN threads
    int b = t >> 12;
    int n = t & (Nsz - 1);

    float acc = 0.0f;
#pragma unroll
    for (int c = 0; c < ICHUNKS; ++c) acc += g_accP[(size_t)c * BN + t];
    float accT = 0.0f;
#pragma unroll
    for (int c = 0; c < JCHUNKS; ++c) accT += g_accTP[(size_t)c * BN + t];

    int r  = refrac[t];
    int rd = (r > 0) ? (r - 1) : r;
    bool active = (rd == 0);

    unsigned m = g_masks[n];
    bool s  = ((m >> b) & 1u) != 0u;
    float mppv = mem_pot_paired[t];
    bool sp = ((mppv - 1.0f) - C_ALPHA) > 0.0f;

    float mp   = mem_pot[t];
    float mc   = mem_cur[t];
    float mcpv = mem_cur_paired[t];

    float mcn  = active ? (inp[t] + acc) + mc : mc;
    float mcpn = active ? accT + mcpv : mcpv;
    float mpn  = active ? mcn + mp : mp;
    float mppn = active ? mcpn + mppv : mppv;

    mpn  *= C_INV_TAU_V;
    mcn  *= C_INV_TAU_I;
    mppn *= C_INV_TAU_V;
    mcpn *= C_INV_TAU_I;

    if (s)  mpn  = 0.0f;
    if (sp) mppn = 0.0f;
    float rn = s ? 2.0f : (float)rd;

    out[OUT_S    + t] = s ? 1.0f : 0.0f;
    out[OUT_POT  + t] = mpn;
    out[OUT_CUR  + t] = mcn;
    out[OUT_POTP + t] = mppn;
    out[OUT_CURP + t] = mcpn;
    out[OUT_REFR + t] = rn;
}

// ---------------------------------------------------------------------------
extern "C" void kernel_launch(void* const* d_in, const int* in_sizes, int n_in,
                              void* d_out, int out_size)
{
    const float* inp      = (const float*)d_in[0];
    const float* W_rec    = (const float*)d_in[1];
    const float* mem_pot  = (const float*)d_in[2];
    const float* mem_cur  = (const float*)d_in[3];
    const float* mpp      = (const float*)d_in[4];
    const float* mcp      = (const float*)d_in[5];
    const float* st       = (const float*)d_in[6];
    const int*   refrac   = (const int*)d_in[7];
    float* out = (float*)d_out;
    float* Wout = out + OUT_W;

    const int smem_bytes = (16384 + 128 * PAD2 + 256) * 4;  // ~133 KB
    cudaFuncSetAttribute(k_fused, cudaFuncAttributeMaxDynamicSharedMemorySize,
                         smem_bytes);

    k_prologue<<<Nsz / 256, 256>>>(mem_pot, mpp, st);
    k_fused<<<dim3(JCHUNKS, ICHUNKS), 512, smem_bytes>>>(W_rec, Wout);
    k_epilogue<<<BN / 256, 256>>>(inp, mem_pot, mem_cur, mpp, mcp, refrac, out);
}

// round 4
// speedup vs baseline: 5.7714x; 2.6583x over previous
#include <cuda_runtime.h>

// ---------------------------------------------------------------------------
// PCritical step, B=32, N=4096 — fused single pass over W, sparse-spike GEMMs.
// Outputs concatenated float32 in reference return order:
//   S (B,N) | mem_pot_n (B,N) | W_new (N,N) | mem_cur_n (B,N) |
//   mem_pot_p_n (B,N) | mem_cur_p_n (B,N) | refrac_new (B,N)
// ---------------------------------------------------------------------------

#define Bsz 32
#define Nsz 4096
#define BN  (Bsz * Nsz)        // 131072
#define NN  (Nsz * Nsz)        // 16777216

#define C_ALPHA 0.025f
#define C_BETA  0.00025f
#define C_TNOW  10.0f
#define C_INV_TAU_V 0.9801986733067553f
#define C_INV_TAU_I 0.36787944117144233f

#define OUT_S    ((long long)0)
#define OUT_POT  ((long long)BN)
#define OUT_W    ((long long)(2LL * BN))
#define OUT_CUR  ((long long)(2LL * BN + NN))
#define OUT_POTP ((long long)(3LL * BN + NN))
#define OUT_CURP ((long long)(4LL * BN + NN))
#define OUT_REFR ((long long)(5LL * BN + NN))

#define ICHUNKS 16             // 4096 / 256  (grid.y)
#define JCHUNKS 32             // 4096 / 128  (grid.x)
#define PITCH   129            // 129 ≡ 1 (mod 32): rows AND columns conflict-free

// scratch (no dynamic allocation allowed)
__device__ __align__(16) unsigned g_masks[Nsz];          // bit b <=> S[b,n]==1
__device__ __align__(16) float    g_e[Nsz];              // exp(max_st/50)
__device__ __align__(16) float    g_ie[Nsz];             // exp(-max_st/50)
__device__ __align__(16) float    g_A[Nsz];              // sp ? ALPHA*e  : 0
__device__ __align__(16) float    g_Ai[Nsz];             // sp ? ALPHA*ie : 0
__device__ __align__(16) float    g_accP[ICHUNKS * BN];  // partials S@W_new
__device__ __align__(16) float    g_accTP[JCHUNKS * BN]; // partials S@W_new^T

// ---------------------------------------------------------------------------
// K1: per-neuron reductions over the batch + exp precompute
// 32 threads x 128 blocks (spread across SMs for latency)
// ---------------------------------------------------------------------------
__global__ void __launch_bounds__(32) k_prologue(
    const float* __restrict__ mem_pot,
    const float* __restrict__ mem_pot_paired,
    const float* __restrict__ st)
{
    int n = blockIdx.x * 32 + threadIdx.x;
    unsigned m = 0u;
    bool anyp = false;
#pragma unroll
    for (int b = 0; b < Bsz; ++b) {
        float mp = mem_pot[b * Nsz + n];
        if (mp > 1.0f) m |= (1u << b);
        float mpp = mem_pot_paired[b * Nsz + n];
        if (((mpp - 1.0f) - C_ALPHA) > 0.0f) anyp = true;
    }
    float stn = st[n];
    float maxst = (m == 0xffffffffu) ? C_TNOW
                : (m ? fmaxf(C_TNOW, stn) : stn);
    float e  = expf(maxst * (1.0f / 50.0f));
    float ie = expf(-maxst * (1.0f / 50.0f));
    g_masks[n] = m;
    g_e[n]  = e;
    g_ie[n] = ie;
    g_A[n]  = anyp ? C_ALPHA * e  : 0.0f;
    g_Ai[n] = anyp ? C_ALPHA * ie : 0.0f;
}

__device__ __forceinline__ float upd1(float w, float A, float Ai, float e, float ie)
{
    float sub = fmaxf(A * ie, Ai * e);        // 0 when row not paired-spiking
    float u = (w + C_BETA) - sub;
    u = fminf(fmaxf(u, 0.0f), 1.0f);
    return (w > 0.0f) ? u : w;                // sign_mask = W_rec > 0
}

// ---------------------------------------------------------------------------
// K2 (fused): W update + both binary-S GEMMs; spike-sparse ffs loops.
// 512 threads, 2 blocks/SM. Tile 256 i x 128 j as 2 subtiles of 128x128.
//   Phase A: coalesced update, tile -> smem c[128][129]
//   Phase B: warp=batch b (+16): acc[b][j]  += c[i][j] over active i (ffs loop)
//   Phase C: warp=batch b (+16): accT[b][i] += c[i][j] over active j (ffs loop)
// Lanes carry the output dim -> every LDS is a full 128B wavefront,
// conflict-free in both row and column direction thanks to PITCH=129.
// ---------------------------------------------------------------------------
__global__ void __launch_bounds__(512, 2) k_fused(
    const float* __restrict__ W, float* __restrict__ Wout)
{
    extern __shared__ float sm[];
    float*    c   = sm;                                  // [128][129]
    unsigned* rbi = (unsigned*)(sm + 128 * PITCH);       // [32][4] rows per b
    unsigned* rbj = rbi + 128;                           // [32][4] cols per b

    const int jc   = blockIdx.x;       // 0..31
    const int ic   = blockIdx.y;       // 0..15
    const int tid  = threadIdx.x;
    const int warp = tid >> 5;         // 0..15
    const int lane = tid & 31;
    const int jg0  = jc * 128;

    // per-column exp factors (block-constant)
    float e0  = g_e[jg0 + lane];       float ie0 = g_ie[jg0 + lane];
    float e1  = g_e[jg0 + lane + 32];  float ie1 = g_ie[jg0 + lane + 32];
    float e2  = g_e[jg0 + lane + 64];  float ie2 = g_ie[jg0 + lane + 64];
    float e3  = g_e[jg0 + lane + 96];  float ie3 = g_ie[jg0 + lane + 96];

    // transposed column masks (block-constant): rbj[b][q] bit r <=> S[b, jg0+q*32+r]
    if (warp < 4) {
        unsigned mw = g_masks[jg0 + warp * 32 + lane];
#pragma unroll
        for (int b = 0; b < 32; ++b) {
            unsigned w = __ballot_sync(0xffffffffu, (mw >> b) & 1u);
            if (lane == b) rbj[b * 4 + warp] = w;
        }
    }

    // Phase-B accumulators persist across both subtiles (same ic chunk)
    float aJ0 = 0, aJ1 = 0, aJ2 = 0, aJ3 = 0;   // b = warp
    float bJ0 = 0, bJ1 = 0, bJ2 = 0, bJ3 = 0;   // b = warp + 16

    const int lp = lane * PITCH;

#pragma unroll
    for (int s = 0; s < 2; ++s) {
        const int ig0 = ic * 256 + s * 128;
        if (s) __syncthreads();        // previous subtile fully consumed

        // ---- Phase A: update 8 contiguous rows per warp ----
#pragma unroll
        for (int r = 0; r < 8; ++r) {
            int il = warp * 8 + r;
            int ig = ig0 + il;
            float A  = g_A[ig];
            float Ai = g_Ai[ig];
            const float* wr = W    + (size_t)ig * Nsz + jg0;
            float*       wo = Wout + (size_t)ig * Nsz + jg0;
            float w0 = wr[lane];
            float w1 = wr[lane + 32];
            float w2 = wr[lane + 64];
            float w3 = wr[lane + 96];
            float u0 = upd1(w0, A, Ai, e0, ie0);
            float u1 = upd1(w1, A, Ai, e1, ie1);
            float u2 = upd1(w2, A, Ai, e2, ie2);
            float u3 = upd1(w3, A, Ai, e3, ie3);
            wo[lane]      = u0;
            wo[lane + 32] = u1;
            wo[lane + 64] = u2;
            wo[lane + 96] = u3;
            float* cr = c + il * PITCH;
            cr[lane]      = u0;
            cr[lane + 32] = u1;
            cr[lane + 64] = u2;
            cr[lane + 96] = u3;
        }
        // transposed row masks for this subtile (warps 4..7)
        if (warp >= 4 && warp < 8) {
            int q = warp - 4;
            unsigned mw = g_masks[ig0 + q * 32 + lane];
#pragma unroll
            for (int b = 0; b < 32; ++b) {
                unsigned w = __ballot_sync(0xffffffffu, (mw >> b) & 1u);
                if (lane == b) rbi[b * 4 + q] = w;
            }
        }
        __syncthreads();

        // ---- Phase B: acc[b][j] over active rows (uniform ffs loop) ----
#pragma unroll
        for (int q = 0; q < 4; ++q) {
            unsigned m = rbi[warp * 4 + q];
            while (m) {
                int r = q * 32 + __ffs(m) - 1; m &= m - 1;
                const float* cr = c + r * PITCH;
                aJ0 += cr[lane];
                aJ1 += cr[lane + 32];
                aJ2 += cr[lane + 64];
                aJ3 += cr[lane + 96];
            }
        }
#pragma unroll
        for (int q = 0; q < 4; ++q) {
            unsigned m = rbi[(warp + 16) * 4 + q];
            while (m) {
                int r = q * 32 + __ffs(m) - 1; m &= m - 1;
                const float* cr = c + r * PITCH;
                bJ0 += cr[lane];
                bJ1 += cr[lane + 32];
                bJ2 += cr[lane + 64];
                bJ3 += cr[lane + 96];
            }
        }

        // ---- Phase C: accT[b][i] over active cols (column reads, no conflicts) ----
        {
            float aI0 = 0, aI1 = 0, aI2 = 0, aI3 = 0;
            float bI0 = 0, bI1 = 0, bI2 = 0, bI3 = 0;
#pragma unroll
            for (int q = 0; q < 4; ++q) {
                unsigned m = rbj[warp * 4 + q];
                while (m) {
                    int j = q * 32 + __ffs(m) - 1; m &= m - 1;
                    const float* cc = c + j + lp;
                    aI0 += cc[0];
                    aI1 += cc[32 * PITCH];
                    aI2 += cc[64 * PITCH];
                    aI3 += cc[96 * PITCH];
                }
            }
#pragma unroll
            for (int q = 0; q < 4; ++q) {
                unsigned m = rbj[(warp + 16) * 4 + q];
                while (m) {
                    int j = q * 32 + __ffs(m) - 1; m &= m - 1;
                    const float* cc = c + j + lp;
                    bI0 += cc[0];
                    bI1 += cc[32 * PITCH];
                    bI2 += cc[64 * PITCH];
                    bI3 += cc[96 * PITCH];
                }
            }
            size_t oa = ((size_t)jc * Bsz + warp) * Nsz + ig0 + lane;
            g_accTP[oa]      = aI0;
            g_accTP[oa + 32] = aI1;
            g_accTP[oa + 64] = aI2;
            g_accTP[oa + 96] = aI3;
            size_t ob = ((size_t)jc * Bsz + warp + 16) * Nsz + ig0 + lane;
            g_accTP[ob]      = bI0;
            g_accTP[ob + 32] = bI1;
            g_accTP[ob + 64] = bI2;
            g_accTP[ob + 96] = bI3;
        }
    }

    // Phase-B partial writes (one per ic chunk)
    {
        size_t oa = ((size_t)ic * Bsz + warp) * Nsz + jg0 + lane;
        g_accP[oa]      = aJ0;
        g_accP[oa + 32] = aJ1;
        g_accP[oa + 64] = aJ2;
        g_accP[oa + 96] = aJ3;
        size_t ob = ((size_t)ic * Bsz + warp + 16) * Nsz + jg0 + lane;
        g_accP[ob]      = bJ0;
        g_accP[ob + 32] = bJ1;
        g_accP[ob + 64] = bJ2;
        g_accP[ob + 96] = bJ3;
    }
}

// ---------------------------------------------------------------------------
// K3: epilogue — reduce partials, integrate, leak, reset, refractory
// ---------------------------------------------------------------------------
__global__ void __launch_bounds__(256) k_epilogue(
    const float* __restrict__ inp,
    const float* __restrict__ mem_pot,
    const float* __restrict__ mem_cur,
    const float* __restrict__ mem_pot_paired,
    const float* __restrict__ mem_cur_paired,
    const int*   __restrict__ refrac,
    float* __restrict__ out)
{
    int t = blockIdx.x * 256 + threadIdx.x;   // BN threads
    int b = t >> 12;
    int n = t & (Nsz - 1);

    float acc = 0.0f;
#pragma unroll
    for (int cN = 0; cN < ICHUNKS; ++cN) acc += g_accP[(size_t)cN * BN + t];
    float accT = 0.0f;
#pragma unroll
    for (int cN = 0; cN < JCHUNKS; ++cN) accT += g_accTP[(size_t)cN * BN + t];

    int r  = refrac[t];
    int rd = (r > 0) ? (r - 1) : r;
    bool active = (rd == 0);

    unsigned m = g_masks[n];
    bool s  = ((m >> b) & 1u) != 0u;
    float mppv = mem_pot_paired[t];
    bool sp = ((mppv - 1.0f) - C_ALPHA) > 0.0f;

    float mp   = mem_pot[t];
    float mc   = mem_cur[t];
    float mcpv = mem_cur_paired[t];

    float mcn  = active ? (inp[t] + acc) + mc : mc;
    float mcpn = active ? accT + mcpv : mcpv;
    float mpn  = active ? mcn + mp : mp;
    float mppn = active ? mcpn + mppv : mppv;

    mpn  *= C_INV_TAU_V;
    mcn  *= C_INV_TAU_I;
    mppn *= C_INV_TAU_V;
    mcpn *= C_INV_TAU_I;

    if (s)  mpn  = 0.0f;
    if (sp) mppn = 0.0f;
    float rn = s ? 2.0f : (float)rd;

    out[OUT_S    + t] = s ? 1.0f : 0.0f;
    out[OUT_POT  + t] = mpn;
    out[OUT_CUR  + t] = mcn;
    out[OUT_POTP + t] = mppn;
    out[OUT_CURP + t] = mcpn;
    out[OUT_REFR + t] = rn;
}

// ---------------------------------------------------------------------------
extern "C" void kernel_launch(void* const* d_in, const int* in_sizes, int n_in,
                              void* d_out, int out_size)
{
    const float* inp      = (const float*)d_in[0];
    const float* W_rec    = (const float*)d_in[1];
    const float* mem_pot  = (const float*)d_in[2];
    const float* mem_cur  = (const float*)d_in[3];
    const float* mpp      = (const float*)d_in[4];
    const float* mcp      = (const float*)d_in[5];
    const float* st       = (const float*)d_in[6];
    const int*   refrac   = (const int*)d_in[7];
    float* out = (float*)d_out;
    float* Wout = out + OUT_W;

    const int smem_bytes = (128 * PITCH + 256) * 4;   // ~67 KB -> 2 blocks/SM
    cudaFuncSetAttribute(k_fused, cudaFuncAttributeMaxDynamicSharedMemorySize,
                         smem_bytes);

    k_prologue<<<Nsz / 32, 32>>>(mem_pot, mpp, st);
    k_fused<<<dim3(JCHUNKS, ICHUNKS), 512, smem_bytes>>>(W_rec, Wout);
    k_epilogue<<<BN / 256, 256>>>(inp, mem_pot, mem_cur, mpp, mcp, refrac, out);
}